// round 1
// baseline (speedup 1.0000x reference)
#include <cuda_runtime.h>

#define L 16384
#define THREADS 512
#define R 32

// XOR swizzle: makes every structured shared-memory pattern below bank-conflict-free.
// Bijection on [0, 16384).
__device__ __forceinline__ int ph(int i) { return i ^ ((i >> 5) & 31); }

// In-register FWHT butterflies over bits [S0, S0+NS) of the register index.
template <int S0, int NS>
__device__ __forceinline__ void fwht_stages(float v[R]) {
#pragma unroll
    for (int s = S0; s < S0 + NS; s++) {
        const int d = 1 << s;
#pragma unroll
        for (int r = 0; r < R; r++) {
            if ((r & d) == 0) {
                float a = v[r];
                float b = v[r + d];
                v[r] = a + b;
                v[r + d] = a - b;
            }
        }
    }
}

extern __shared__ float sh[];

__global__ void __launch_bounds__(THREADS) ff_kernel(
    const float* __restrict__ x,
    const float* __restrict__ Bv,
    const float* __restrict__ Gv,
    const int* __restrict__ Pi,
    float* __restrict__ out)
{
    const int t = threadIdx.x;
    const int l = t & 31;       // lane
    const int w = t >> 5;       // warp, 0..15
    const int row = blockIdx.x;
    const float* xr = x + (size_t)row * L;
    float* outr = out + (size_t)row * L;

    float v[R];
    const int base = t * R;     // natural (P1) layout: i = t*32 + r

    // ---- load x * B (coalesced float4) ----
#pragma unroll
    for (int c = 0; c < 8; c++) {
        float4 xv = *reinterpret_cast<const float4*>(xr + base + c * 4);
        float4 bv = *reinterpret_cast<const float4*>(Bv + base + c * 4);
        v[c * 4 + 0] = xv.x * bv.x;
        v[c * 4 + 1] = xv.y * bv.y;
        v[c * 4 + 2] = xv.z * bv.z;
        v[c * 4 + 3] = xv.w * bv.w;
    }

    // ================= FWHT #1 =================
    // P1: bits 0-4 in registers
    fwht_stages<0, 5>(v);
#pragma unroll
    for (int r = 0; r < R; r++) sh[ph(base + r)] = v[r];
    __syncthreads();

    // P2: bits 5-9 in registers.  i = w*1024 + r*32 + l
#pragma unroll
    for (int r = 0; r < R; r++) v[r] = sh[ph(w * 1024 + r * 32 + l)];
    fwht_stages<0, 5>(v);
    // each thread writes back exactly the addresses it read: no sync needed in between
#pragma unroll
    for (int r = 0; r < R; r++) sh[ph(w * 1024 + r * 32 + l)] = v[r];
    __syncthreads();

    // P3: bits 10-13 in registers (bit 9 rides along as passenger).
    // i = (r&15)*1024 + (r>>4)*512 + w*32 + l
#pragma unroll
    for (int r = 0; r < R; r++)
        v[r] = sh[ph((r & 15) * 1024 + (r >> 4) * 512 + w * 32 + l)];
    fwht_stages<0, 4>(v);
#pragma unroll
    for (int r = 0; r < R; r++)
        sh[ph((r & 15) * 1024 + (r >> 4) * 512 + w * 32 + l)] = v[r];
    __syncthreads();

    // ---- permutation gather + gain + combined scale (1/sqrt(N))^2 = 1/16384 ----
    constexpr float SC = 1.0f / 16384.0f;
#pragma unroll
    for (int c = 0; c < 8; c++) {
        int4   p = *reinterpret_cast<const int4*>(Pi + base + c * 4);
        float4 g = *reinterpret_cast<const float4*>(Gv + base + c * 4);
        v[c * 4 + 0] = sh[ph(p.x)] * (g.x * SC);
        v[c * 4 + 1] = sh[ph(p.y)] * (g.y * SC);
        v[c * 4 + 2] = sh[ph(p.z)] * (g.z * SC);
        v[c * 4 + 3] = sh[ph(p.w)] * (g.w * SC);
    }

    // ================= FWHT #2 =================
    // P1 (gather already delivered natural layout: regs = bits 0-4)
    fwht_stages<0, 5>(v);
    __syncthreads();   // all gathers of y1 complete before overwriting sh
#pragma unroll
    for (int r = 0; r < R; r++) sh[ph(base + r)] = v[r];
    __syncthreads();

    // P2
#pragma unroll
    for (int r = 0; r < R; r++) v[r] = sh[ph(w * 1024 + r * 32 + l)];
    fwht_stages<0, 5>(v);
#pragma unroll
    for (int r = 0; r < R; r++) sh[ph(w * 1024 + r * 32 + l)] = v[r];
    __syncthreads();

    // P3
#pragma unroll
    for (int r = 0; r < R; r++)
        v[r] = sh[ph((r & 15) * 1024 + (r >> 4) * 512 + w * 32 + l)];
    fwht_stages<0, 4>(v);

    // ---- final store: P3 layout is lane-consecutive -> coalesced STG.32 ----
#pragma unroll
    for (int r = 0; r < R; r++)
        outr[(r & 15) * 1024 + (r >> 4) * 512 + w * 32 + l] = v[r];
}

extern "C" void kernel_launch(void* const* d_in, const int* in_sizes, int n_in,
                              void* d_out, int out_size)
{
    const float* x  = (const float*)d_in[0];
    const float* B  = (const float*)d_in[1];
    const float* G  = (const float*)d_in[2];
    const int*   Pi = (const int*)d_in[3];
    float* out = (float*)d_out;

    const int rows = in_sizes[0] / L;   // 4096

    // 64 KB dynamic shared per CTA (above the 48 KB static limit): opt in every call
    // (idempotent, deterministic, not a stream op — safe under graph capture).
    cudaFuncSetAttribute(ff_kernel, cudaFuncAttributeMaxDynamicSharedMemorySize, L * (int)sizeof(float));

    ff_kernel<<<rows, THREADS, L * sizeof(float)>>>(x, B, G, Pi, out);
}